// round 2
// baseline (speedup 1.0000x reference)
#include <cuda_runtime.h>

// Shapes (fixed by problem)
#define Bc   512
#define Sc   64
#define Nc   8
#define Ac   16
#define Hc   256
#define OBSc 512          // N*D
#define RS   68           // padded row stride for transposed h1 tile (16B-aligned: 68*4=272=16*17)

// Shared-memory layout (in floats)
#define OFF_H1T   0                      // 256 * 68 = 17408 floats
#define OFF_PA    (OFF_H1T + 256*RS)     // 8*8*256 = 16384 floats
#define OFF_STATE (OFF_PA + 16384)       // 512
#define OFF_ACT   (OFF_STATE + 512)      // 128
#define OFF_RED4  (OFF_ACT + 128)        // 256
#define OFF_ROWQ  (OFF_RED4 + 256)       // 64
#define OFF_PERM  (OFF_ROWQ + 64)        // 64 ints
#define SMEM_FLOATS (OFF_PERM + 64)
#define SMEM_BYTES  (SMEM_FLOATS * 4)

// mish(x) = x*tanh(softplus(x)) = x*(u^2-1)/(u^2+1), u = 1+e^x
__device__ __forceinline__ float mish_f(float x) {
    float e  = __expf(fminf(x, 15.0f));
    float u  = 1.0f + e;
    float u2 = u * u;
    return x * __fdividef(u2 - 1.0f, u2 + 1.0f);
}

__device__ __forceinline__ void fma_f32x2(unsigned long long &d,
                                          unsigned long long a,
                                          unsigned long long b,
                                          unsigned long long c) {
    asm("fma.rn.f32x2 %0, %1, %2, %3;" : "=l"(d) : "l"(a), "l"(b), "l"(c));
}

__device__ __forceinline__ unsigned long long pack2(float lo, float hi) {
    unsigned long long r;
    asm("mov.b64 %0, {%1, %2};" : "=l"(r) : "f"(lo), "f"(hi));
    return r;
}

__device__ __forceinline__ float lo32(unsigned long long v) {
    return __uint_as_float((unsigned int)(v & 0xffffffffull));
}
__device__ __forceinline__ float hi32(unsigned long long v) {
    return __uint_as_float((unsigned int)(v >> 32));
}

// One block handles (b, half-of-S). 256 threads; thread == hidden index h / h'.
__global__ void __launch_bounds__(256, 1)
shapley_main(const float* __restrict__ state,   // (B, N, D)
             const float* __restrict__ action,  // (B, N, A)
             const float* __restrict__ W1,      // (640, 256)
             const float* __restrict__ b1,      // (256)
             const float* __restrict__ W2,      // (256, 256)
             const float* __restrict__ b2,      // (256)
             const float* __restrict__ W3,      // (256, 1)
             const float* __restrict__ b3,      // (1)
             const int*   __restrict__ perm,    // (B, S, N)
             float*       __restrict__ out)     // (B, N) accumulated atomically
{
    const int tid  = threadIdx.x;
    const int bx   = blockIdx.x;
    const int b    = bx >> 1;
    const int soff = (bx & 1) * 32;

    extern __shared__ float sm[];
    float* sH1T   = sm + OFF_H1T;
    float* sPA    = sm + OFF_PA;
    float* sState = sm + OFF_STATE;
    float* sAct   = sm + OFF_ACT;
    float* sRed4  = sm + OFF_RED4;
    float* sRowQ  = sm + OFF_ROWQ;
    int*   sPerm  = (int*)(sm + OFF_PERM);

    // ---- load per-b inputs ----
    sState[tid]       = state[b * OBSc + tid];
    sState[256 + tid] = state[b * OBSc + 256 + tid];
    if (tid < 128) sAct[tid] = action[b * (Nc * Ac) + tid];
    __syncthreads();

    // ---- obs1[h] = b1[h] + state_flat . W1[0:512, h]  (kept in register) ----
    float o = b1[tid];
    #pragma unroll 8
    for (int k = 0; k < OBSc; ++k)
        o = fmaf(sState[k], __ldg(&W1[k * Hc + tid]), o);

    // ---- PA[j][n][h] = action[b,n] . W1[512+16j : 512+16(j+1), h] ----
    #pragma unroll
    for (int j = 0; j < 8; ++j) {
        float pa[8] = {0.f, 0.f, 0.f, 0.f, 0.f, 0.f, 0.f, 0.f};
        #pragma unroll
        for (int k = 0; k < 16; ++k) {
            float wv = __ldg(&W1[(OBSc + j * 16 + k) * Hc + tid]);
            #pragma unroll
            for (int n = 0; n < 8; ++n)
                pa[n] = fmaf(sAct[n * 16 + k], wv, pa[n]);
        }
        #pragma unroll
        for (int n = 0; n < 8; ++n)
            sPA[(j * 8 + n) * Hc + tid] = pa[n];
    }

    const float b2t = b2[tid];
    const float w3t = W3[tid];
    const float b3v = b3[0];
    float qsum = 0.0f;   // valid for tid < 8 (thread i accumulates q1[b,i]*S over groups)
    __syncthreads();

    // ---- 4 groups of 8 s-values (64 rows per group) ----
    for (int g = 0; g < 4; ++g) {
        // load perm for this group of 8 s-values
        if (tid < 64) {
            int sl = tid >> 3, j = tid & 7;
            sPerm[tid] = perm[((b * Sc) + soff + g * 8 + sl) * Nc + j];
        }
        __syncthreads();

        // layer 1: prefix-sum of PA rows, mish, write transposed h1 tile
        #pragma unroll
        for (int sl = 0; sl < 8; ++sl) {
            float pref = 0.0f;
            #pragma unroll
            for (int t = 0; t < 8; ++t) {
                int pj = sPerm[sl * 8 + t];
                pref += sPA[(t * 8 + pj) * Hc + tid];
                sH1T[tid * RS + sl * 8 + t] = mish_f(o + pref);
            }
        }
        __syncthreads();

        // layer 2: thread tid owns output column h' = tid, 64 rows via f32x2 accumulators
        unsigned long long acc[32];
        #pragma unroll
        for (int p = 0; p < 32; ++p) acc[p] = 0ull;

        #pragma unroll 4
        for (int h = 0; h < Hc; ++h) {
            float w = __ldg(&W2[h * Hc + tid]);
            unsigned long long ww = pack2(w, w);
            const ulonglong2* hp =
                reinterpret_cast<const ulonglong2*>(sH1T + h * RS);
            #pragma unroll
            for (int q = 0; q < 16; ++q) {
                ulonglong2 hv = hp[q];
                fma_f32x2(acc[2 * q],     hv.x, ww, acc[2 * q]);
                fma_f32x2(acc[2 * q + 1], hv.y, ww, acc[2 * q + 1]);
            }
        }
        __syncthreads();   // all reads of sH1T done; safe to overwrite

        // finalize: z -> mish -> * W3[h'], stash per-(row, h') into sH1T
        #pragma unroll
        for (int p = 0; p < 32; ++p) {
            float zl = lo32(acc[p]) + b2t;
            float zh = hi32(acc[p]) + b2t;
            sH1T[tid * RS + 2 * p]     = mish_f(zl) * w3t;
            sH1T[tid * RS + 2 * p + 1] = mish_f(zh) * w3t;
        }
        __syncthreads();

        // reduce over h' (256) for each of 64 rows: 4 partials per row
        {
            int r = tid >> 2, c = tid & 3;
            float q = 0.0f;
            #pragma unroll 8
            for (int h = c * 64; h < c * 64 + 64; ++h)
                q += sH1T[h * RS + r];
            sRed4[tid] = q;
        }
        __syncthreads();
        if (tid < 64) {
            float q = b3v + sRed4[4 * tid] + sRed4[4 * tid + 1]
                          + sRed4[4 * tid + 2] + sRed4[4 * tid + 3];
            sRowQ[tid] = q;   // row = sl*8 + t
        }
        __syncthreads();

        // map rows back: q1[b,i] += q~[s, t = perm[b,s,i]]
        if (tid < 8) {
            #pragma unroll
            for (int sl = 0; sl < 8; ++sl) {
                int t = sPerm[sl * 8 + tid];
                qsum += sRowQ[sl * 8 + t];
            }
        }
        __syncthreads();
    }

    if (tid < 8)
        atomicAdd(&out[b * Nc + tid], qsum * (1.0f / 64.0f));
}

// duplicate q1 into the second half of the output tuple
__global__ void dup_out_kernel(float* __restrict__ out) {
    int i = blockIdx.x * blockDim.x + threadIdx.x;
    if (i < Bc * Nc) out[Bc * Nc + i] = out[i];
}

extern "C" void kernel_launch(void* const* d_in, const int* in_sizes, int n_in,
                              void* d_out, int out_size) {
    const float* state  = (const float*)d_in[0];
    const float* action = (const float*)d_in[1];
    const float* W1     = (const float*)d_in[2];
    const float* b1     = (const float*)d_in[3];
    const float* W2     = (const float*)d_in[4];
    const float* b2     = (const float*)d_in[5];
    const float* W3     = (const float*)d_in[6];
    const float* b3     = (const float*)d_in[7];
    const int*   perm   = (const int*)  d_in[8];
    float* out = (float*)d_out;

    cudaFuncSetAttribute(shapley_main,
                         cudaFuncAttributeMaxDynamicSharedMemorySize,
                         SMEM_BYTES);

    // zero the q1 region (harness poisons d_out); atomic accumulation follows
    int zelems = (out_size < Bc * Nc) ? out_size : (Bc * Nc);
    cudaMemsetAsync(d_out, 0, (size_t)zelems * sizeof(float), 0);

    shapley_main<<<Bc * 2, 256, SMEM_BYTES>>>(state, action, W1, b1, W2, b2,
                                              W3, b3, perm, out);

    if (out_size >= 2 * Bc * Nc)
        dup_out_kernel<<<(Bc * Nc + 255) / 256, 256>>>(out);
}

// round 6
// speedup vs baseline: 3.0506x; 3.0506x over previous
#include <cuda_runtime.h>
#include <cuda_bf16.h>
#include <cstdint>

// ---------------- problem shapes ----------------
#define Bc   512
#define Sc   64
#define Nc   8
#define Ac   16
#define Hc   256
#define OBSc 512

// smem strides (words)
#define BSTR  264    // per B n-row (pair-interleaved k)
#define PASTR 260    // per PA row

// ---------------- device scratch ----------------
__device__ __align__(16) float g_BT[2][128 * BSTR];   // tf32 bits of W2^T, per n-half
__device__ __align__(16) float g_PA2[Bc * 64 * 256];  // PA rows, obs1 folded into u=0 rows

// ---------------- helpers ----------------
__device__ __forceinline__ float mish_f(float x) {
    float e  = __expf(fminf(x, 15.0f));
    float u  = 1.0f + e;
    float u2 = u * u;
    return x * __fdividef(u2 - 1.0f, u2 + 1.0f);
}
__device__ __forceinline__ uint32_t to_tf32(float f) {
    uint32_t r;
    asm("cvt.rna.tf32.f32 %0, %1;" : "=r"(r) : "f"(f));
    return r;
}

// m16n8k8 tf32 mma; C is a float4 variable (fields = registers, no arrays)
#define MMA_TF32(C, a0, a1, a2, a3, b0, b1)                                  \
    asm volatile("mma.sync.aligned.m16n8k8.row.col.f32.tf32.tf32.f32 "      \
        "{%0,%1,%2,%3}, {%4,%5,%6,%7}, {%8,%9}, {%0,%1,%2,%3};"             \
        : "+f"(C.x), "+f"(C.y), "+f"(C.z), "+f"(C.w)                        \
        : "r"(a0), "r"(a1), "r"(a2), "r"(a3), "r"(b0), "r"(b1))

// pair-interleaved k index: within each 8-k group, (k, k+4) adjacent
__device__ __host__ __forceinline__ int kinterleave(int k) {
    return (k & ~7) + 2 * (k & 3) + ((k >> 2) & 1);
}

// ================= prep 1: W2 -> tf32 W2^T images =================
__global__ void prep_w2_kernel(const float* __restrict__ W2) {
    int idx = blockIdx.x * blockDim.x + threadIdx.x;   // 65536
    if (idx >= Hc * Hc) return;
    int k = idx >> 8, n = idx & 255;
    uint32_t v = to_tf32(W2[idx]);                     // W2[k][n]
    g_BT[n >> 7][(n & 127) * BSTR + kinterleave(k)] = __uint_as_float(v);
}

// ================= prep 2: PA rows with obs folded =================
__global__ void __launch_bounds__(256)
prep_obs_pa_kernel(const float* __restrict__ state,
                   const float* __restrict__ action,
                   const float* __restrict__ W1,
                   const float* __restrict__ b1) {
    __shared__ float sState[4 * OBSc];
    __shared__ float sAct[4 * 128];
    const int tid = threadIdx.x;
    const int b0  = blockIdx.x * 4;

    for (int i = tid; i < 4 * OBSc; i += 256) sState[i] = state[b0 * OBSc + i];
    for (int i = tid; i < 4 * 128;  i += 256) sAct[i]   = action[b0 * 128 + i];
    __syncthreads();

    const int h = tid;
    float ob0 = b1[h], ob1 = ob0, ob2 = ob0, ob3 = ob0;
    for (int k = 0; k < OBSc; ++k) {
        float w = __ldg(&W1[k * Hc + h]);
        ob0 = fmaf(sState[k],            w, ob0);
        ob1 = fmaf(sState[OBSc + k],     w, ob1);
        ob2 = fmaf(sState[2 * OBSc + k], w, ob2);
        ob3 = fmaf(sState[3 * OBSc + k], w, ob3);
    }

    for (int j = 0; j < 8; ++j) {          // runtime loop; small scalar state
        for (int n = 0; n < 8; ++n) {
            float p0 = 0.f, p1 = 0.f, p2 = 0.f, p3 = 0.f;
            #pragma unroll
            for (int k = 0; k < 16; ++k) {
                float w = __ldg(&W1[(OBSc + j * 16 + k) * Hc + h]);
                p0 = fmaf(sAct[0 * 128 + n * 16 + k], w, p0);
                p1 = fmaf(sAct[1 * 128 + n * 16 + k], w, p1);
                p2 = fmaf(sAct[2 * 128 + n * 16 + k], w, p2);
                p3 = fmaf(sAct[3 * 128 + n * 16 + k], w, p3);
            }
            if (j == 0) { p0 += ob0; p1 += ob1; p2 += ob2; p3 += ob3; }
            g_PA2[((b0 + 0) * 64 + j * 8 + n) * 256 + h] = p0;
            g_PA2[((b0 + 1) * 64 + j * 8 + n) * 256 + h] = p1;
            g_PA2[((b0 + 2) * 64 + j * 8 + n) * 256 + h] = p2;
            g_PA2[((b0 + 3) * 64 + j * 8 + n) * 256 + h] = p3;
        }
    }
}

// ================= main fused kernel =================
// grid 1024: (b = bx>>1, nh = bx&1). 256 threads, 8 warps.
// GEMM rows r = t*64 + s. Warp tile: 16 rows x 128 cols; 4 passes.
#define OFF_B    0
#define SZ_B     (128 * BSTR * 4)          // 135168
#define OFF_PA   (OFF_B + SZ_B)
#define SZ_PA    (64 * PASTR * 4)          // 66560
#define OFF_PERM (OFF_PA + SZ_PA)          // 512 ints
#define OFF_ROWQ (OFF_PERM + 2048)         // 512 f
#define OFF_B2   (OFF_ROWQ + 2048)         // 128 f
#define OFF_W3   (OFF_B2 + 512)            // 128 f
#define OFF_RED  (OFF_W3 + 512)            // 256 f
#define SMEM_MAIN (OFF_RED + 1024)         // 207360 B

__global__ void __launch_bounds__(256, 1)
shapley_mma(const float* __restrict__ b2,
            const float* __restrict__ W3,
            const float* __restrict__ b3,
            const int*   __restrict__ perm,
            float*       __restrict__ out) {
    extern __shared__ char smem[];
    const int tid  = threadIdx.x;
    const int wid  = tid >> 5;
    const int lane = tid & 31;
    const int b    = blockIdx.x >> 1;
    const int nh   = blockIdx.x & 1;

    float* sB    = (float*)(smem + OFF_B);
    float* sPA   = (float*)(smem + OFF_PA);
    int*   sPerm = (int*)  (smem + OFF_PERM);
    float* sRowQ = (float*)(smem + OFF_ROWQ);
    float* sB2   = (float*)(smem + OFF_B2);
    float* sW3   = (float*)(smem + OFF_W3);
    float* sRed  = (float*)(smem + OFF_RED);

    // ---- stage B ----
    {
        const uint4* src = (const uint4*)g_BT[nh];
        uint4* dst = (uint4*)sB;
        for (int i = tid; i < (128 * BSTR) / 4; i += 256) dst[i] = src[i];
    }
    // ---- stage PA ----
    {
        const float* src = g_PA2 + b * (64 * 256);
        for (int idx = tid; idx < 64 * 256; idx += 256) {
            int r = idx >> 8, h = idx & 255;
            sPA[r * PASTR + h] = src[idx];
        }
    }
    for (int i = tid; i < Sc * Nc; i += 256) sPerm[i] = perm[b * (Sc * Nc) + i];
    if (tid < 128) {
        sB2[tid] = b2[nh * 128 + tid];
        sW3[tid] = W3[nh * 128 + tid];
    }
    const float b3v = b3[0];
    __syncthreads();

    const int lam = lane >> 2;    // fragment row within group (0..7)
    const int kq  = lane & 3;     // fragment k sub-index (0..3)

    #pragma unroll 1
    for (int p = 0; p < 4; ++p) {
        const int R  = p * 128 + wid * 16;     // first row of warp tile
        const int t  = R >> 6;                 // warp-uniform prefix cutoff (0..7)
        const int sa = (R & 63) + lam;         // s of row lam
        const int sb = sa + 8;                 // s of row lam+8

        // prefix row bases: 16 named scalars, unconditionally initialized
        int rbA0, rbA1, rbA2, rbA3, rbA4, rbA5, rbA6, rbA7;
        int rbB0, rbB1, rbB2, rbB3, rbB4, rbB5, rbB6, rbB7;
#define RBI(u) rbA##u = (u * 8 + sPerm[sa * 8 + u]) * PASTR; \
               rbB##u = (u * 8 + sPerm[sb * 8 + u]) * PASTR;
        RBI(0) RBI(1) RBI(2) RBI(3) RBI(4) RBI(5) RBI(6) RBI(7)
#undef RBI

        // accumulators: 16 named float4 (never subscripted / address-taken)
        float4 C0  = {0,0,0,0}, C1  = {0,0,0,0}, C2  = {0,0,0,0}, C3  = {0,0,0,0};
        float4 C4  = {0,0,0,0}, C5  = {0,0,0,0}, C6  = {0,0,0,0}, C7  = {0,0,0,0};
        float4 C8  = {0,0,0,0}, C9  = {0,0,0,0}, C10 = {0,0,0,0}, C11 = {0,0,0,0};
        float4 C12 = {0,0,0,0}, C13 = {0,0,0,0}, C14 = {0,0,0,0}, C15 = {0,0,0,0};

        #pragma unroll 1
        for (int ks = 0; ks < 32; ++ks) {
            const int kb = ks * 8 + kq;
            float x00 = sPA[rbA0 + kb], x01 = sPA[rbA0 + kb + 4];
            float x10 = sPA[rbB0 + kb], x11 = sPA[rbB0 + kb + 4];
#define PSUM(u) if (t >= u) { x00 += sPA[rbA##u + kb]; x01 += sPA[rbA##u + kb + 4]; \
                              x10 += sPA[rbB##u + kb]; x11 += sPA[rbB##u + kb + 4]; }
            PSUM(1) PSUM(2) PSUM(3) PSUM(4) PSUM(5) PSUM(6) PSUM(7)
#undef PSUM
            const uint32_t a0 = to_tf32(mish_f(x00));   // row lam,   k
            const uint32_t a1 = to_tf32(mish_f(x10));   // row lam+8, k
            const uint32_t a2 = to_tf32(mish_f(x01));   // row lam,   k+4
            const uint32_t a3 = to_tf32(mish_f(x11));   // row lam+8, k+4
            const int bof = ks * 8 + 2 * kq;
#define BMMA(nt) { float2 bb = *(const float2*)&sB[((nt) * 8 + lam) * BSTR + bof]; \
                   MMA_TF32(C##nt, a0, a1, a2, a3, \
                            __float_as_uint(bb.x), __float_as_uint(bb.y)); }
            BMMA(0)  BMMA(1)  BMMA(2)  BMMA(3)
            BMMA(4)  BMMA(5)  BMMA(6)  BMMA(7)
            BMMA(8)  BMMA(9)  BMMA(10) BMMA(11)
            BMMA(12) BMMA(13) BMMA(14) BMMA(15)
#undef BMMA
        }

        // ---- epilogue: mish(z+b2)*w3, row-sum over this CTA's 128 cols ----
        float rs0 = 0.f, rs1 = 0.f;
#define EPI(nt) { const int c0 = (nt) * 8 + kq * 2;                               \
    rs0 += mish_f(C##nt.x + sB2[c0])     * sW3[c0]                                \
         + mish_f(C##nt.y + sB2[c0 + 1]) * sW3[c0 + 1];                           \
    rs1 += mish_f(C##nt.z + sB2[c0])     * sW3[c0]                                \
         + mish_f(C##nt.w + sB2[c0 + 1]) * sW3[c0 + 1]; }
        EPI(0)  EPI(1)  EPI(2)  EPI(3)
        EPI(4)  EPI(5)  EPI(6)  EPI(7)
        EPI(8)  EPI(9)  EPI(10) EPI(11)
        EPI(12) EPI(13) EPI(14) EPI(15)
#undef EPI
        rs0 += __shfl_xor_sync(0xffffffffu, rs0, 1);
        rs0 += __shfl_xor_sync(0xffffffffu, rs0, 2);
        rs1 += __shfl_xor_sync(0xffffffffu, rs1, 1);
        rs1 += __shfl_xor_sync(0xffffffffu, rs1, 2);
        if (kq == 0) {
            sRowQ[R + lam]     = rs0 + 0.5f * b3v;
            sRowQ[R + lam + 8] = rs1 + 0.5f * b3v;
        }
    }
    __syncthreads();

    // ---- gather q1 partials: (s,i) -> row = perm[s,i]*64 + s ----
    {
        const int i = tid & 7, s = tid >> 3;
        float v0 = 0.f, v1 = 0.f;
        int t0 = sPerm[s * 8 + i];
        int t1 = sPerm[(s + 32) * 8 + i];
        v0 = sRowQ[t0 * 64 + s];
        v1 = sRowQ[t1 * 64 + s + 32];
        sRed[tid] = v0 + v1;
    }
    __syncthreads();
    if (tid < 8) {
        float sum = 0.0f;
        #pragma unroll 8
        for (int g = 0; g < 32; ++g) sum += sRed[g * 8 + tid];
        atomicAdd(&out[b * Nc + tid], sum * (1.0f / 64.0f));
    }
}

// duplicate q1 into second half of the output tuple
__global__ void dup_out_kernel(float* __restrict__ out) {
    int i = blockIdx.x * blockDim.x + threadIdx.x;
    if (i < Bc * Nc) out[Bc * Nc + i] = out[i];
}

extern "C" void kernel_launch(void* const* d_in, const int* in_sizes, int n_in,
                              void* d_out, int out_size) {
    const float* state  = (const float*)d_in[0];
    const float* action = (const float*)d_in[1];
    const float* W1     = (const float*)d_in[2];
    const float* b1     = (const float*)d_in[3];
    const float* W2     = (const float*)d_in[4];
    const float* b2     = (const float*)d_in[5];
    const float* W3     = (const float*)d_in[6];
    const float* b3     = (const float*)d_in[7];
    const int*   perm   = (const int*)  d_in[8];
    float* out = (float*)d_out;

    cudaFuncSetAttribute(shapley_mma,
                         cudaFuncAttributeMaxDynamicSharedMemorySize, SMEM_MAIN);

    prep_w2_kernel<<<256, 256>>>(W2);
    prep_obs_pa_kernel<<<128, 256>>>(state, action, W1, b1);

    int zelems = (out_size < Bc * Nc) ? out_size : (Bc * Nc);
    cudaMemsetAsync(d_out, 0, (size_t)zelems * sizeof(float), 0);

    shapley_mma<<<Bc * 2, 256, SMEM_MAIN>>>(b2, W3, b3, perm, out);

    if (out_size >= 2 * Bc * Nc)
        dup_out_kernel<<<(Bc * Nc + 255) / 256, 256>>>(out);
}

// round 7
// speedup vs baseline: 3.7424x; 1.2268x over previous
#include <cuda_runtime.h>
#include <cuda_fp16.h>
#include <cstdint>

// ---------------- problem shapes ----------------
#define Bc   512
#define Sc   64
#define Nc   8
#define Ac   16
#define Hc   256
#define OBSc 512

// smem strides (words)
#define BSTR2 136    // uint32 words per B column (16 chunks * 8 + pad 8)
#define PASTR 260    // floats per PA row

// ---------------- device scratch ----------------
__device__ __align__(16) uint32_t g_B16[2][128 * BSTR2]; // fp16x2 W2 image per n-half
__device__ __align__(16) float    g_PA2[Bc * 64 * 256];  // PA rows, obs1 folded into u=0

// ---------------- helpers ----------------
// mish(x) = x * (1 - 2/(u^2+1)), u = 1+e^x ; reciprocal via bit-hack + 2 Newton
__device__ __forceinline__ float mish_f(float x) {
    float e  = __expf(fminf(x, 15.0f));
    float u  = 1.0f + e;
    float d  = fmaf(u, u, 1.0f);                 // u^2 + 1  (>= 2)
    float r  = __uint_as_float(0x7EF477D5u - __float_as_uint(d));
    r = r * (2.0f - d * r);
    r = r * (2.0f - d * r);
    return x * (1.0f - 2.0f * r);
}

// pack two f32 -> f16x2 register (lo in low half)
__device__ __forceinline__ uint32_t h2pack(float lo, float hi) {
    uint32_t r;
    asm("cvt.rn.f16x2.f32 %0, %1, %2;" : "=r"(r) : "f"(hi), "f"(lo));
    return r;
}

// m16n8k16 fp16 mma, f32 accumulate; C is a float4 variable (regs only)
#define MMA_F16(C, a0, a1, a2, a3, b0, b1)                                    \
    asm volatile("mma.sync.aligned.m16n8k16.row.col.f32.f16.f16.f32 "        \
        "{%0,%1,%2,%3}, {%4,%5,%6,%7}, {%8,%9}, {%0,%1,%2,%3};"              \
        : "+f"(C.x), "+f"(C.y), "+f"(C.z), "+f"(C.w)                         \
        : "r"(a0), "r"(a1), "r"(a2), "r"(a3), "r"(b0), "r"(b1))

// ================= prep 1: W2 -> fp16x2 packed B images =================
// word layout per column: idx = chunk*8 + 2*tg + hi  (chunk=k>>4, tg=(k>>1)&3, hi=(k>>3)&1)
__global__ void prep_w2_kernel(const float* __restrict__ W2) {
    int idx = blockIdx.x * blockDim.x + threadIdx.x;   // 2*128*128 = 32768 words
    if (idx >= 2 * 128 * 128) return;
    int nhalf = idx >> 14;
    int rem   = idx & 16383;
    int col   = rem >> 7;
    int w     = rem & 127;
    int chunk = w >> 3;
    int tg    = (w >> 1) & 3;
    int hi    = w & 1;
    int k0    = chunk * 16 + hi * 8 + tg * 2;
    int n     = nhalf * 128 + col;
    float lo = W2[k0 * Hc + n];
    float hif = W2[(k0 + 1) * Hc + n];
    g_B16[nhalf][col * BSTR2 + w] = h2pack(lo, hif);
}

// ================= prep 2: PA rows with obs folded =================
__global__ void __launch_bounds__(256)
prep_obs_pa_kernel(const float* __restrict__ state,
                   const float* __restrict__ action,
                   const float* __restrict__ W1,
                   const float* __restrict__ b1) {
    __shared__ float sState[4 * OBSc];
    __shared__ float sAct[4 * 128];
    const int tid = threadIdx.x;
    const int b0  = blockIdx.x * 4;

    for (int i = tid; i < 4 * OBSc; i += 256) sState[i] = state[b0 * OBSc + i];
    for (int i = tid; i < 4 * 128;  i += 256) sAct[i]   = action[b0 * 128 + i];
    __syncthreads();

    const int h = tid;
    float ob0 = b1[h], ob1 = ob0, ob2 = ob0, ob3 = ob0;
    for (int k = 0; k < OBSc; ++k) {
        float w = __ldg(&W1[k * Hc + h]);
        ob0 = fmaf(sState[k],            w, ob0);
        ob1 = fmaf(sState[OBSc + k],     w, ob1);
        ob2 = fmaf(sState[2 * OBSc + k], w, ob2);
        ob3 = fmaf(sState[3 * OBSc + k], w, ob3);
    }

    for (int j = 0; j < 8; ++j) {
        for (int n = 0; n < 8; ++n) {
            float p0 = 0.f, p1 = 0.f, p2 = 0.f, p3 = 0.f;
            #pragma unroll
            for (int k = 0; k < 16; ++k) {
                float w = __ldg(&W1[(OBSc + j * 16 + k) * Hc + h]);
                p0 = fmaf(sAct[0 * 128 + n * 16 + k], w, p0);
                p1 = fmaf(sAct[1 * 128 + n * 16 + k], w, p1);
                p2 = fmaf(sAct[2 * 128 + n * 16 + k], w, p2);
                p3 = fmaf(sAct[3 * 128 + n * 16 + k], w, p3);
            }
            if (j == 0) { p0 += ob0; p1 += ob1; p2 += ob2; p3 += ob3; }
            g_PA2[((b0 + 0) * 64 + j * 8 + n) * 256 + h] = p0;
            g_PA2[((b0 + 1) * 64 + j * 8 + n) * 256 + h] = p1;
            g_PA2[((b0 + 2) * 64 + j * 8 + n) * 256 + h] = p2;
            g_PA2[((b0 + 3) * 64 + j * 8 + n) * 256 + h] = p3;
        }
    }
}

// ================= main fused kernel =================
// grid 1024: (b = bx>>1, nh = bx&1). 256 threads, 8 warps.
// rows r = t*64 + s. Warp tile: 16 rows x 128 cols; 4 passes; K chunks of 16.
#define OFF_B    0
#define SZ_B     (128 * BSTR2 * 4)         // 69632
#define OFF_PA   (OFF_B + SZ_B)
#define SZ_PA    (64 * PASTR * 4)          // 66560
#define OFF_PERM (OFF_PA + SZ_PA)          // 512 ints
#define OFF_ROWQ (OFF_PERM + 2048)         // 512 f
#define OFF_B2   (OFF_ROWQ + 2048)         // 128 f
#define OFF_W3   (OFF_B2 + 512)            // 128 f
#define OFF_RED  (OFF_W3 + 512)            // 256 f
#define SMEM_MAIN (OFF_RED + 1024)         // 142848 B

__global__ void __launch_bounds__(256, 1)
shapley_mma(const float* __restrict__ b2,
            const float* __restrict__ W3,
            const float* __restrict__ b3,
            const int*   __restrict__ perm,
            float*       __restrict__ out) {
    extern __shared__ char smem[];
    const int tid  = threadIdx.x;
    const int wid  = tid >> 5;
    const int lane = tid & 31;
    const int b    = blockIdx.x >> 1;
    const int nh   = blockIdx.x & 1;

    uint32_t* sB  = (uint32_t*)(smem + OFF_B);
    float* sPA   = (float*)(smem + OFF_PA);
    int*   sPerm = (int*)  (smem + OFF_PERM);
    float* sRowQ = (float*)(smem + OFF_ROWQ);
    float* sB2   = (float*)(smem + OFF_B2);
    float* sW3   = (float*)(smem + OFF_W3);
    float* sRed  = (float*)(smem + OFF_RED);

    // ---- stage B (69632 B linear) ----
    {
        const uint4* src = (const uint4*)g_B16[nh];
        uint4* dst = (uint4*)sB;
        for (int i = tid; i < (128 * BSTR2) / 4; i += 256) dst[i] = src[i];
    }
    // ---- stage PA ----
    {
        const float* src = g_PA2 + b * (64 * 256);
        for (int idx = tid; idx < 64 * 256; idx += 256) {
            int r = idx >> 8, h = idx & 255;
            sPA[r * PASTR + h] = src[idx];
        }
    }
    for (int i = tid; i < Sc * Nc; i += 256) sPerm[i] = perm[b * (Sc * Nc) + i];
    if (tid < 128) {
        sB2[tid] = b2[nh * 128 + tid];
        sW3[tid] = W3[nh * 128 + tid];
    }
    const float b3v = b3[0];
    __syncthreads();

    const int lam = lane >> 2;    // fragment row group (0..7)
    const int kq  = lane & 3;     // fragment k sub-index (0..3)

    #pragma unroll 1
    for (int p = 0; p < 4; ++p) {
        const int R  = p * 128 + wid * 16;     // first row of warp tile
        const int t  = R >> 6;                 // warp-uniform prefix cutoff (0..7)
        const int sa = (R & 63) + lam;         // s of row lam
        const int sb = sa + 8;                 // s of row lam+8

        int rbA0, rbA1, rbA2, rbA3, rbA4, rbA5, rbA6, rbA7;
        int rbB0, rbB1, rbB2, rbB3, rbB4, rbB5, rbB6, rbB7;
#define RBI(u) rbA##u = (u * 8 + sPerm[sa * 8 + u]) * PASTR; \
               rbB##u = (u * 8 + sPerm[sb * 8 + u]) * PASTR;
        RBI(0) RBI(1) RBI(2) RBI(3) RBI(4) RBI(5) RBI(6) RBI(7)
#undef RBI

        float4 C0  = {0,0,0,0}, C1  = {0,0,0,0}, C2  = {0,0,0,0}, C3  = {0,0,0,0};
        float4 C4  = {0,0,0,0}, C5  = {0,0,0,0}, C6  = {0,0,0,0}, C7  = {0,0,0,0};
        float4 C8  = {0,0,0,0}, C9  = {0,0,0,0}, C10 = {0,0,0,0}, C11 = {0,0,0,0};
        float4 C12 = {0,0,0,0}, C13 = {0,0,0,0}, C14 = {0,0,0,0}, C15 = {0,0,0,0};

        #pragma unroll 1
        for (int ch = 0; ch < 16; ++ch) {
            const int kb = ch * 16 + 2 * kq;   // low k of this lane's pair
            // prefix sums (float2 paired loads; k and k+1 adjacent)
            float2 vA0 = *(const float2*)&sPA[rbA0 + kb];
            float2 vA8 = *(const float2*)&sPA[rbA0 + kb + 8];
            float2 vB0 = *(const float2*)&sPA[rbB0 + kb];
            float2 vB8 = *(const float2*)&sPA[rbB0 + kb + 8];
            float xA0 = vA0.x, xA1 = vA0.y, xA8 = vA8.x, xA9 = vA8.y;
            float xB0 = vB0.x, xB1 = vB0.y, xB8 = vB8.x, xB9 = vB8.y;
#define PSUM(u) if (t >= u) {                                                 \
    float2 wA0 = *(const float2*)&sPA[rbA##u + kb];                           \
    float2 wA8 = *(const float2*)&sPA[rbA##u + kb + 8];                       \
    float2 wB0 = *(const float2*)&sPA[rbB##u + kb];                           \
    float2 wB8 = *(const float2*)&sPA[rbB##u + kb + 8];                       \
    xA0 += wA0.x; xA1 += wA0.y; xA8 += wA8.x; xA9 += wA8.y;                   \
    xB0 += wB0.x; xB1 += wB0.y; xB8 += wB8.x; xB9 += wB8.y; }
            PSUM(1) PSUM(2) PSUM(3) PSUM(4) PSUM(5) PSUM(6) PSUM(7)
#undef PSUM
            const uint32_t a0 = h2pack(mish_f(xA0), mish_f(xA1));
            const uint32_t a1 = h2pack(mish_f(xB0), mish_f(xB1));
            const uint32_t a2 = h2pack(mish_f(xA8), mish_f(xA9));
            const uint32_t a3 = h2pack(mish_f(xB8), mish_f(xB9));
            const int bof = ch * 8 + 2 * kq;
#define BMMA(nt) { uint2 bb = *(const uint2*)&sB[((nt) * 8 + lam) * BSTR2 + bof]; \
                   MMA_F16(C##nt, a0, a1, a2, a3, bb.x, bb.y); }
            BMMA(0)  BMMA(1)  BMMA(2)  BMMA(3)
            BMMA(4)  BMMA(5)  BMMA(6)  BMMA(7)
            BMMA(8)  BMMA(9)  BMMA(10) BMMA(11)
            BMMA(12) BMMA(13) BMMA(14) BMMA(15)
#undef BMMA
        }

        // ---- epilogue: mish(z+b2)*w3, row-sum over this CTA's 128 cols ----
        float rs0 = 0.f, rs1 = 0.f;
#define EPI(nt) { const int c0 = (nt) * 8 + kq * 2;                               \
    rs0 += mish_f(C##nt.x + sB2[c0])     * sW3[c0]                                \
         + mish_f(C##nt.y + sB2[c0 + 1]) * sW3[c0 + 1];                           \
    rs1 += mish_f(C##nt.z + sB2[c0])     * sW3[c0]                                \
         + mish_f(C##nt.w + sB2[c0 + 1]) * sW3[c0 + 1]; }
        EPI(0)  EPI(1)  EPI(2)  EPI(3)
        EPI(4)  EPI(5)  EPI(6)  EPI(7)
        EPI(8)  EPI(9)  EPI(10) EPI(11)
        EPI(12) EPI(13) EPI(14) EPI(15)
#undef EPI
        rs0 += __shfl_xor_sync(0xffffffffu, rs0, 1);
        rs0 += __shfl_xor_sync(0xffffffffu, rs0, 2);
        rs1 += __shfl_xor_sync(0xffffffffu, rs1, 1);
        rs1 += __shfl_xor_sync(0xffffffffu, rs1, 2);
        if (kq == 0) {
            sRowQ[R + lam]     = rs0 + 0.5f * b3v;
            sRowQ[R + lam + 8] = rs1 + 0.5f * b3v;
        }
    }
    __syncthreads();

    // ---- gather q1 partials: (s,i) -> row = perm[s,i]*64 + s ----
    {
        const int i = tid & 7, s = tid >> 3;
        int t0 = sPerm[s * 8 + i];
        int t1 = sPerm[(s + 32) * 8 + i];
        sRed[tid] = sRowQ[t0 * 64 + s] + sRowQ[t1 * 64 + s + 32];
    }
    __syncthreads();
    if (tid < 8) {
        float sum = 0.0f;
        #pragma unroll 8
        for (int g = 0; g < 32; ++g) sum += sRed[g * 8 + tid];
        atomicAdd(&out[b * Nc + tid], sum * (1.0f / 64.0f));
    }
}

// duplicate q1 into second half of the output tuple
__global__ void dup_out_kernel(float* __restrict__ out) {
    int i = blockIdx.x * blockDim.x + threadIdx.x;
    if (i < Bc * Nc) out[Bc * Nc + i] = out[i];
}

extern "C" void kernel_launch(void* const* d_in, const int* in_sizes, int n_in,
                              void* d_out, int out_size) {
    const float* state  = (const float*)d_in[0];
    const float* action = (const float*)d_in[1];
    const float* W1     = (const float*)d_in[2];
    const float* b1     = (const float*)d_in[3];
    const float* W2     = (const float*)d_in[4];
    const float* b2     = (const float*)d_in[5];
    const float* W3     = (const float*)d_in[6];
    const float* b3     = (const float*)d_in[7];
    const int*   perm   = (const int*)  d_in[8];
    float* out = (float*)d_out;

    cudaFuncSetAttribute(shapley_mma,
                         cudaFuncAttributeMaxDynamicSharedMemorySize, SMEM_MAIN);

    prep_w2_kernel<<<128, 256>>>(W2);
    prep_obs_pa_kernel<<<128, 256>>>(state, action, W1, b1);

    int zelems = (out_size < Bc * Nc) ? out_size : (Bc * Nc);
    cudaMemsetAsync(d_out, 0, (size_t)zelems * sizeof(float), 0);

    shapley_mma<<<Bc * 2, 256, SMEM_MAIN>>>(b2, W3, b3, perm, out);

    if (out_size >= 2 * Bc * Nc)
        dup_out_kernel<<<(Bc * Nc + 255) / 256, 256>>>(out);
}